// round 16
// baseline (speedup 1.0000x reference)
#include <cuda_runtime.h>
#include <cuda_bf16.h>
#include <mma.h>
#include <cstdint>

using namespace nvcuda;

#define N_NODES 50000
#define N_EDGES 600000
#define FEAT 128
#define PADM 50048        // 782 * 64
#define CAP 64            // bucket capacity per node (P(deg>=64) ~ 1e-30)
#define NTILES 782
#define TILES_C0 391      // chunk 0: tiles [0,391)   = nodes [0,25024)
#define NODES_C0 25024

// ---------------- device scratch ----------------
__device__ int   g_idx64;
__device__ int   g_pos_arange;
__device__ int   g_cnt[N_NODES];
__device__ int   g_bucket[(size_t)N_NODES * CAP];   // 12.8 MB adjacency buckets

__device__ float g_agg[(size_t)PADM * FEAT];   // fp32 aggregated features (pads stay 0)
__device__ float g_h1 [(size_t)PADM * FEAT];   // fp32 layer-1 output (pads stay 0)
// B[layer][n][k], k in [0,256): k<128 -> Wl[k][n], else Wr[k-128][n]
__device__ __nv_bfloat16 g_Bhi[2 * 128 * 256];
__device__ __nv_bfloat16 g_Blo[2 * 128 * 256];

__device__ __forceinline__ int load_idx(const void* p, long long i, int is64) {
    return is64 ? (int)((const long long*)p)[i] : ((const int*)p)[i];
}
__device__ __forceinline__ unsigned pack_bf16x2(float a, float b) {
    unsigned short ua = __bfloat16_as_ushort(__float2bfloat16_rn(a));
    unsigned short ub = __bfloat16_as_ushort(__float2bfloat16_rn(b));
    return (unsigned)ua | ((unsigned)ub << 16);
}
__device__ __forceinline__ float bf16v(float v) {
    return __bfloat162float(__float2bfloat16_rn(v));
}
__device__ __forceinline__ uint32_t smem_u32(const void* p) {
    uint32_t a;
    asm("{ .reg .u64 t; cvta.to.shared.u64 t, %1; cvt.u32.u64 %0, t; }" : "=r"(a) : "l"(p));
    return a;
}
#define CP_ASYNC16(dst_u32, src_ptr) \
    asm volatile("cp.async.cg.shared.global [%0], [%1], 16;" :: "r"(dst_u32), "l"(src_ptr))
#define CP_COMMIT() asm volatile("cp.async.commit_group;" ::: "memory")
#define CP_WAIT0()  asm volatile("cp.async.wait_group 0;" ::: "memory")

// ---------------- detect (block 0) + reset counters (all blocks) ----------------
__global__ void k_detect_reset(const unsigned* __restrict__ w, const void* __restrict__ pos) {
    int tid = threadIdx.x;
    if (blockIdx.x == 0) {
        int ok64 = (w[2 * tid + 1] == 0u) ? 1 : 0;
        int is64 = __syncthreads_and(ok64);
        if (tid == 0) g_idx64 = is64;
        int idx = tid * 195;     // spans [0, 49725]
        int ar = (load_idx(pos, idx, is64) == idx) ? 1 : 0;
        int arall = __syncthreads_and(ar);
        if (tid == 0) g_pos_arange = arall;
    }
    int i = blockIdx.x * blockDim.x + tid;
    if (i < N_NODES) g_cnt[i] = 0;
}

// ---------------- init (side stream): zero out-tail + prep weights ----------------
__global__ void k_init(float* __restrict__ out, int out_n,
                       const float* __restrict__ Wl1, const float* __restrict__ Wr1,
                       const float* __restrict__ Wl2, const float* __restrict__ Wr2) {
    int stride = gridDim.x * blockDim.x;
    int gid = blockIdx.x * blockDim.x + threadIdx.x;

    float4 z = make_float4(0.f, 0.f, 0.f, 0.f);
    int zstart4 = g_pos_arange ? (N_NODES * FEAT) >> 2 : 0;
    int on4 = out_n >> 2;
    for (int i = zstart4 + gid; i < on4; i += stride) ((float4*)out)[i] = z;

    for (int id = gid; id < 2 * 128 * 256; id += stride) {
        int layer = id >> 15;
        int rem = id & 32767;
        int n = rem >> 8;
        int k = rem & 255;
        const float* Wl = layer ? Wl2 : Wl1;
        const float* Wr = layer ? Wr2 : Wr1;
        float v = (k < 128) ? Wl[k * 128 + n] : Wr[(k - 128) * 128 + n];
        __nv_bfloat16 h = __float2bfloat16_rn(v);
        g_Bhi[id] = h;
        g_Blo[id] = __float2bfloat16_rn(v - __bfloat162float(h));
    }
}

// ---------------- fused hist+scatter: atomic return value IS the bucket slot ----------------
__global__ void k_build(const void* __restrict__ ei) {
    int e = blockIdx.x * blockDim.x + threadIdx.x;
    if (e >= N_EDGES) return;
    int is64 = g_idx64;
    int s = load_idx(ei, e, is64);
    int d = load_idx(ei, (long long)N_EDGES + e, is64);
    if ((unsigned)d >= (unsigned)N_NODES || (unsigned)s >= (unsigned)N_NODES) return;
    int p = atomicAdd(&g_cnt[d], 1);
    if (p < CAP) g_bucket[(size_t)d * CAP + p] = s;
}

// ---------------- aggregation: one warp per node in [n0,n1), 4-way unrolled gather ----------------
__global__ void k_agg(const float* __restrict__ feat_x, int layer2, int n0, int n1) {
    const float* __restrict__ feat = layer2 ? g_h1 : feat_x;
    int gw = n0 + ((blockIdx.x * blockDim.x + threadIdx.x) >> 5);
    int lane = threadIdx.x & 31;
    if (gw >= n1) return;
    int cnt = g_cnt[gw];
    int e = min(cnt, CAP);
    const int* __restrict__ adj = g_bucket + (size_t)gw * CAP;
    float4 acc = make_float4(0.f, 0.f, 0.f, 0.f);
    int i = 0;
    for (; i + 4 <= e; i += 4) {
        int s0 = adj[i + 0], s1 = adj[i + 1], s2 = adj[i + 2], s3 = adj[i + 3];
        float4 v0 = *(const float4*)(feat + (size_t)s0 * FEAT + lane * 4);
        float4 v1 = *(const float4*)(feat + (size_t)s1 * FEAT + lane * 4);
        float4 v2 = *(const float4*)(feat + (size_t)s2 * FEAT + lane * 4);
        float4 v3 = *(const float4*)(feat + (size_t)s3 * FEAT + lane * 4);
        acc.x += v0.x + v1.x + v2.x + v3.x;
        acc.y += v0.y + v1.y + v2.y + v3.y;
        acc.z += v0.z + v1.z + v2.z + v3.z;
        acc.w += v0.w + v1.w + v2.w + v3.w;
    }
    for (; i < e; i++) {
        int src = adj[i];
        float4 v = *(const float4*)(feat + (size_t)src * FEAT + lane * 4);
        acc.x += v.x; acc.y += v.y; acc.z += v.z; acc.w += v.w;
    }
    float inv = 1.0f / fmaxf((float)cnt, 1.0f);
    acc.x *= inv; acc.y *= inv; acc.z *= inv; acc.w *= inv;
    *(float4*)(g_agg + (size_t)gw * FEAT + lane * 4) = acc;
}

// ---------------- cp.async double-buffered bf16 3-split wmma GEMM (64x128 tile) ----------------
typedef wmma::fragment<wmma::matrix_a, 16, 16, 16, __nv_bfloat16, wmma::row_major> FragA;
typedef wmma::fragment<wmma::matrix_b, 16, 16, 16, __nv_bfloat16, wmma::col_major> FragB;
typedef wmma::fragment<wmma::accumulator, 16, 16, 16, float> FragC;

#define KP 40          // padded k-stride in smem (elements)
#define BUF_BYTES 30720
#define GEMM_SMEM (2 * BUF_BYTES)   // 61440; epilogue (64x128 f32 = 32768) reuses buf0

__global__ void __launch_bounds__(256) k_gemm(
    const float* __restrict__ xin,
    const float* __restrict__ bias,
    float* __restrict__ out2, const void* __restrict__ pos, int layer2, int tile_base)
{
    extern __shared__ __align__(16) char smraw[];
    const float* selfF = layer2 ? g_h1 : xin;
    const __nv_bfloat16* BH = g_Bhi + (size_t)layer2 * 128 * 256;
    const __nv_bfloat16* BL = g_Blo + (size_t)layer2 * 128 * 256;

    int tid = threadIdx.x;
    int warp = tid >> 5;
    int wm = warp & 1;    // 2 M warps (32 rows each)
    int wn = warp >> 1;   // 4 N warps (32 cols each)
    int m0 = (tile_base + blockIdx.x) * 64;

    int r = tid >> 2;          // 0..63 (A tile row)
    int cc = tid & 3;          // 0..3
    bool arow_ok = (m0 + r) < N_NODES;
    uint32_t sbase = smem_u32(smraw);

    #define A_PTR(ch) (((ch) < 4 ? g_agg : selfF) + (size_t)(m0 + r) * FEAT + ((ch) & 3) * 32 + cc * 8)
    #define ISSUE_B(ch, b) do {                                                    \
        int _bk = (ch) * 32;                                                       \
        _Pragma("unroll")                                                          \
        for (int _j = 0; _j < 2; _j++) {                                           \
            int _seg = tid + _j * 256;                                             \
            int _rb = _seg >> 2, _cb = _seg & 3;                                   \
            size_t _bsrc = (size_t)_rb * 256 + _bk + _cb * 8;                      \
            uint32_t _dst = sbase + (b) * BUF_BYTES + 10240 + (_rb * KP + _cb * 8) * 2; \
            CP_ASYNC16(_dst, BH + _bsrc);                                          \
            CP_ASYNC16(_dst + 10240, BL + _bsrc);                                  \
        }                                                                          \
        CP_COMMIT();                                                               \
    } while (0)
    #define STORE_A(b, f0, f1) do {                                                \
        uint4 _hv, _lv;                                                            \
        _hv.x = pack_bf16x2((f0).x, (f0).y);                                       \
        _hv.y = pack_bf16x2((f0).z, (f0).w);                                       \
        _hv.z = pack_bf16x2((f1).x, (f1).y);                                       \
        _hv.w = pack_bf16x2((f1).z, (f1).w);                                       \
        _lv.x = pack_bf16x2((f0).x - bf16v((f0).x), (f0).y - bf16v((f0).y));       \
        _lv.y = pack_bf16x2((f0).z - bf16v((f0).z), (f0).w - bf16v((f0).w));       \
        _lv.z = pack_bf16x2((f1).x - bf16v((f1).x), (f1).y - bf16v((f1).y));       \
        _lv.w = pack_bf16x2((f1).z - bf16v((f1).z), (f1).w - bf16v((f1).w));       \
        __nv_bfloat16* _sA0 = (__nv_bfloat16*)(smraw + (b) * BUF_BYTES);           \
        __nv_bfloat16* _sA1 = (__nv_bfloat16*)(smraw + (b) * BUF_BYTES + 5120);    \
        int _dstA = r * KP + cc * 8;                                               \
        *(uint4*)(_sA0 + _dstA) = _hv;                                             \
        *(uint4*)(_sA1 + _dstA) = _lv;                                             \
    } while (0)

    // prologue: stage chunk 0 into buffer 0
    ISSUE_B(0, 0);
    float4 f0 = make_float4(0.f, 0.f, 0.f, 0.f), f1 = f0;
    if (arow_ok) {
        const float* p = A_PTR(0);
        f0 = *(const float4*)p;
        f1 = *(const float4*)(p + 4);
    }
    STORE_A(0, f0, f1);
    CP_WAIT0();
    __syncthreads();

    FragC c[2][2];
    #pragma unroll
    for (int i = 0; i < 2; i++)
        #pragma unroll
        for (int j = 0; j < 2; j++)
            wmma::fill_fragment(c[i][j], 0.0f);

    #pragma unroll 1
    for (int ch = 0; ch < 8; ch++) {
        int cur = ch & 1, nxt = cur ^ 1;

        float4 n0 = make_float4(0.f, 0.f, 0.f, 0.f), n1 = n0;
        if (ch < 7) {
            ISSUE_B(ch + 1, nxt);
            if (arow_ok) {
                const float* p = A_PTR(ch + 1);
                n0 = *(const float4*)p;
                n1 = *(const float4*)(p + 4);
            }
        }

        __nv_bfloat16* sA0 = (__nv_bfloat16*)(smraw + cur * BUF_BYTES);
        __nv_bfloat16* sA1 = (__nv_bfloat16*)(smraw + cur * BUF_BYTES + 5120);
        __nv_bfloat16* sB0 = (__nv_bfloat16*)(smraw + cur * BUF_BYTES + 10240);
        __nv_bfloat16* sB1 = (__nv_bfloat16*)(smraw + cur * BUF_BYTES + 20480);
        #pragma unroll
        for (int ks = 0; ks < 2; ks++) {
            FragA ah[2], al[2];
            #pragma unroll
            for (int i = 0; i < 2; i++) {
                wmma::load_matrix_sync(ah[i], sA0 + (wm * 32 + i * 16) * KP + ks * 16, KP);
                wmma::load_matrix_sync(al[i], sA1 + (wm * 32 + i * 16) * KP + ks * 16, KP);
            }
            FragB bh[2], bl[2];
            #pragma unroll
            for (int j = 0; j < 2; j++) {
                wmma::load_matrix_sync(bh[j], sB0 + (wn * 32 + j * 16) * KP + ks * 16, KP);
                wmma::load_matrix_sync(bl[j], sB1 + (wn * 32 + j * 16) * KP + ks * 16, KP);
            }
            #pragma unroll
            for (int i = 0; i < 2; i++)
                #pragma unroll
                for (int j = 0; j < 2; j++) {
                    wmma::mma_sync(c[i][j], ah[i], bh[j], c[i][j]);
                    wmma::mma_sync(c[i][j], al[i], bh[j], c[i][j]);
                    wmma::mma_sync(c[i][j], ah[i], bl[j], c[i][j]);
                }
        }

        if (ch < 7) {
            STORE_A(nxt, n0, n1);
            CP_WAIT0();
        }
        __syncthreads();
    }

    // epilogue: single-pass 64 x 128 f32 through smem (reuses buffers)
    float* cs = (float*)smraw;
    int is64 = g_idx64;
    #pragma unroll
    for (int i = 0; i < 2; i++)
        #pragma unroll
        for (int j = 0; j < 2; j++)
            wmma::store_matrix_sync(&cs[(wm * 32 + i * 16) * 128 + wn * 32 + j * 16],
                                    c[i][j], 128, wmma::mem_row_major);
    __syncthreads();

    #pragma unroll
    for (int it = 0; it < 8; it++) {
        int idx = (it * 256 + tid) * 4;    // 0..8188 -> 64x128
        int m = idx >> 7;
        int n = idx & 127;
        int row = m0 + m;
        if (row < N_NODES) {
            float v0 = fmaxf(cs[idx + 0] + bias[n + 0], 0.0f);
            float v1 = fmaxf(cs[idx + 1] + bias[n + 1], 0.0f);
            float v2 = fmaxf(cs[idx + 2] + bias[n + 2], 0.0f);
            float v3 = fmaxf(cs[idx + 3] + bias[n + 3], 0.0f);
            if (!layer2) {
                *(float4*)(g_h1 + (size_t)row * FEAT + n) = make_float4(v0, v1, v2, v3);
            } else {
                long long orow = (long long)load_idx(pos, row, is64);
                *(float4*)(out2 + (size_t)orow * FEAT + n) = make_float4(v0, v1, v2, v3);
            }
        }
    }
}

// ---------------- launch: 2-chunk agg/gemm pipeline across two streams ----------------
extern "C" void kernel_launch(void* const* d_in, const int* in_sizes, int n_in,
                              void* d_out, int out_size) {
    int wi = (n_in >= 10) ? 4 : 3;
    const float* x   = (const float*)d_in[0];
    const void*  ei  = d_in[1];
    const void*  pos = d_in[2];
    const float* Wl1 = (const float*)d_in[wi + 0];
    const float* Wr1 = (const float*)d_in[wi + 1];
    const float* b1  = (const float*)d_in[wi + 2];
    const float* Wl2 = (const float*)d_in[wi + 3];
    const float* Wr2 = (const float*)d_in[wi + 4];
    const float* b2  = (const float*)d_in[wi + 5];
    float* out = (float*)d_out;

    static cudaStream_t s_side = nullptr, s_agg = nullptr;
    static cudaEvent_t ev_fork = nullptr, ev_join = nullptr, ev_build = nullptr;
    static cudaEvent_t ev_a1[2], ev_a2[2], ev_g1 = nullptr;
    static int done_init = 0;
    if (!done_init) {
        cudaFuncSetAttribute(k_gemm, cudaFuncAttributeMaxDynamicSharedMemorySize, GEMM_SMEM);
        cudaStreamCreateWithFlags(&s_side, cudaStreamNonBlocking);
        cudaStreamCreateWithFlags(&s_agg, cudaStreamNonBlocking);
        cudaEventCreateWithFlags(&ev_fork, cudaEventDisableTiming);
        cudaEventCreateWithFlags(&ev_join, cudaEventDisableTiming);
        cudaEventCreateWithFlags(&ev_build, cudaEventDisableTiming);
        cudaEventCreateWithFlags(&ev_g1, cudaEventDisableTiming);
        for (int i = 0; i < 2; i++) {
            cudaEventCreateWithFlags(&ev_a1[i], cudaEventDisableTiming);
            cudaEventCreateWithFlags(&ev_a2[i], cudaEventDisableTiming);
        }
        done_init = 1;
    }

    const int AGG_BLK_C0 = (NODES_C0 * 32 + 255) / 256;               // chunk0 warps
    const int AGG_BLK_C1 = ((N_NODES - NODES_C0) * 32 + 255) / 256;   // chunk1 warps

    // stream 0: detect + reset feeds everything
    k_detect_reset<<<(N_NODES + 255) / 256, 256>>>((const unsigned*)ei, pos);

    // fork: init (weights + out-zero) beside build/agg
    cudaEventRecord(ev_fork, 0);
    cudaStreamWaitEvent(s_side, ev_fork, 0);
    k_init<<<2048, 256, 0, s_side>>>(out, out_size, Wl1, Wr1, Wl2, Wr2);
    cudaEventRecord(ev_join, s_side);

    // adjacency build on stream 0
    k_build<<<(N_EDGES + 255) / 256, 256>>>(ei);
    cudaEventRecord(ev_build, 0);

    // ---- layer 1 pipeline: agg chunks on s_agg, gemm chunks on stream 0 ----
    cudaStreamWaitEvent(s_agg, ev_build, 0);
    k_agg<<<AGG_BLK_C0, 256, 0, s_agg>>>(x, 0, 0, NODES_C0);
    cudaEventRecord(ev_a1[0], s_agg);
    k_agg<<<AGG_BLK_C1, 256, 0, s_agg>>>(x, 0, NODES_C0, N_NODES);
    cudaEventRecord(ev_a1[1], s_agg);

    cudaStreamWaitEvent(0, ev_join, 0);     // weights ready
    cudaStreamWaitEvent(0, ev_a1[0], 0);
    k_gemm<<<TILES_C0, 256, GEMM_SMEM>>>(x, b1, nullptr, nullptr, 0, 0);
    cudaStreamWaitEvent(0, ev_a1[1], 0);
    k_gemm<<<NTILES - TILES_C0, 256, GEMM_SMEM>>>(x, b1, nullptr, nullptr, 0, TILES_C0);
    cudaEventRecord(ev_g1, 0);

    // ---- layer 2 pipeline (agg2 needs ALL of gemm1) ----
    cudaStreamWaitEvent(s_agg, ev_g1, 0);
    k_agg<<<AGG_BLK_C0, 256, 0, s_agg>>>(x, 1, 0, NODES_C0);
    cudaEventRecord(ev_a2[0], s_agg);
    k_agg<<<AGG_BLK_C1, 256, 0, s_agg>>>(x, 1, NODES_C0, N_NODES);
    cudaEventRecord(ev_a2[1], s_agg);

    cudaStreamWaitEvent(0, ev_a2[0], 0);
    k_gemm<<<TILES_C0, 256, GEMM_SMEM>>>(x, b2, out, pos, 1, 0);
    cudaStreamWaitEvent(0, ev_a2[1], 0);
    k_gemm<<<NTILES - TILES_C0, 256, GEMM_SMEM>>>(x, b2, out, pos, 1, TILES_C0);
}

// round 17
// speedup vs baseline: 1.0375x; 1.0375x over previous
#include <cuda_runtime.h>
#include <cuda_bf16.h>
#include <mma.h>
#include <cstdint>

using namespace nvcuda;

#define N_NODES 50000
#define N_EDGES 600000
#define FEAT 128
#define PADM 50048        // 782 * 64
#define CAP 64            // bucket capacity per node (P(deg>=64) ~ 1e-30)
#define NTILES 782

// ---------------- device scratch ----------------
__device__ int   g_idx64;
__device__ int   g_pos_arange;
__device__ int   g_cnt[N_NODES];
__device__ int   g_bucket[(size_t)N_NODES * CAP];   // 12.8 MB adjacency buckets

__device__ float g_agg[(size_t)PADM * FEAT];   // fp32 aggregated features (pads stay 0)
__device__ float g_h1 [(size_t)PADM * FEAT];   // fp32 layer-1 output (pads stay 0)
// B[layer][n][k], k in [0,256): k<128 -> Wl[k][n], else Wr[k-128][n]
__device__ __nv_bfloat16 g_Bhi[2 * 128 * 256];
__device__ __nv_bfloat16 g_Blo[2 * 128 * 256];

__device__ __forceinline__ int load_idx(const void* p, long long i, int is64) {
    return is64 ? (int)((const long long*)p)[i] : ((const int*)p)[i];
}
__device__ __forceinline__ unsigned pack_bf16x2(float a, float b) {
    unsigned short ua = __bfloat16_as_ushort(__float2bfloat16_rn(a));
    unsigned short ub = __bfloat16_as_ushort(__float2bfloat16_rn(b));
    return (unsigned)ua | ((unsigned)ub << 16);
}
__device__ __forceinline__ float bf16v(float v) {
    return __bfloat162float(__float2bfloat16_rn(v));
}
__device__ __forceinline__ uint32_t smem_u32(const void* p) {
    uint32_t a;
    asm("{ .reg .u64 t; cvta.to.shared.u64 t, %1; cvt.u32.u64 %0, t; }" : "=r"(a) : "l"(p));
    return a;
}
#define CP_ASYNC16(dst_u32, src_ptr) \
    asm volatile("cp.async.cg.shared.global [%0], [%1], 16;" :: "r"(dst_u32), "l"(src_ptr))
#define CP_COMMIT() asm volatile("cp.async.commit_group;" ::: "memory")
#define CP_WAIT0()  asm volatile("cp.async.wait_group 0;" ::: "memory")

// ---------------- detect (block 0) + reset counters (all blocks) ----------------
__global__ void k_detect_reset(const unsigned* __restrict__ w, const void* __restrict__ pos) {
    int tid = threadIdx.x;
    if (blockIdx.x == 0) {
        int ok64 = (w[2 * tid + 1] == 0u) ? 1 : 0;
        int is64 = __syncthreads_and(ok64);
        if (tid == 0) g_idx64 = is64;
        int idx = tid * 195;     // spans [0, 49725]
        int ar = (load_idx(pos, idx, is64) == idx) ? 1 : 0;
        int arall = __syncthreads_and(ar);
        if (tid == 0) g_pos_arange = arall;
    }
    int i = blockIdx.x * blockDim.x + tid;
    if (i < N_NODES) g_cnt[i] = 0;
}

// ---------------- init (side stream): zero out-tail + prep weights ----------------
__global__ void k_init(float* __restrict__ out, int out_n,
                       const float* __restrict__ Wl1, const float* __restrict__ Wr1,
                       const float* __restrict__ Wl2, const float* __restrict__ Wr2) {
    int stride = gridDim.x * blockDim.x;
    int gid = blockIdx.x * blockDim.x + threadIdx.x;

    float4 z = make_float4(0.f, 0.f, 0.f, 0.f);
    int zstart4 = g_pos_arange ? (N_NODES * FEAT) >> 2 : 0;
    int on4 = out_n >> 2;
    for (int i = zstart4 + gid; i < on4; i += stride) ((float4*)out)[i] = z;

    for (int id = gid; id < 2 * 128 * 256; id += stride) {
        int layer = id >> 15;
        int rem = id & 32767;
        int n = rem >> 8;
        int k = rem & 255;
        const float* Wl = layer ? Wl2 : Wl1;
        const float* Wr = layer ? Wr2 : Wr1;
        float v = (k < 128) ? Wl[k * 128 + n] : Wr[(k - 128) * 128 + n];
        __nv_bfloat16 h = __float2bfloat16_rn(v);
        g_Bhi[id] = h;
        g_Blo[id] = __float2bfloat16_rn(v - __bfloat162float(h));
    }
}

// ---------------- fused hist+scatter: atomic return value IS the bucket slot ----------------
__global__ void k_build(const void* __restrict__ ei) {
    int e = blockIdx.x * blockDim.x + threadIdx.x;
    if (e >= N_EDGES) return;
    int is64 = g_idx64;
    int s = load_idx(ei, e, is64);
    int d = load_idx(ei, (long long)N_EDGES + e, is64);
    if ((unsigned)d >= (unsigned)N_NODES || (unsigned)s >= (unsigned)N_NODES) return;
    int p = atomicAdd(&g_cnt[d], 1);
    if (p < CAP) g_bucket[(size_t)d * CAP + p] = s;
}

// ---------------- aggregation: one warp per node, 8-wide unrolled gather (MLP=8) ----------------
__global__ void k_agg(const float* __restrict__ feat_x, int layer2) {
    const float* __restrict__ feat = layer2 ? g_h1 : feat_x;
    int gw = (blockIdx.x * blockDim.x + threadIdx.x) >> 5;
    int lane = threadIdx.x & 31;
    if (gw >= N_NODES) return;
    int cnt = g_cnt[gw];
    int e = min(cnt, CAP);
    const int* __restrict__ adj = g_bucket + (size_t)gw * CAP;
    float4 acc = make_float4(0.f, 0.f, 0.f, 0.f);
    int i = 0;
    for (; i + 8 <= e; i += 8) {
        int idx[8];
        #pragma unroll
        for (int j = 0; j < 8; j++) idx[j] = adj[i + j];
        float4 v[8];
        #pragma unroll
        for (int j = 0; j < 8; j++)
            v[j] = *(const float4*)(feat + (size_t)idx[j] * FEAT + lane * 4);
        // pairwise tree sum (short dependency chains)
        float4 s01, s23, s45, s67, s0123, s4567;
        s01.x = v[0].x + v[1].x; s01.y = v[0].y + v[1].y; s01.z = v[0].z + v[1].z; s01.w = v[0].w + v[1].w;
        s23.x = v[2].x + v[3].x; s23.y = v[2].y + v[3].y; s23.z = v[2].z + v[3].z; s23.w = v[2].w + v[3].w;
        s45.x = v[4].x + v[5].x; s45.y = v[4].y + v[5].y; s45.z = v[4].z + v[5].z; s45.w = v[4].w + v[5].w;
        s67.x = v[6].x + v[7].x; s67.y = v[6].y + v[7].y; s67.z = v[6].z + v[7].z; s67.w = v[6].w + v[7].w;
        s0123.x = s01.x + s23.x; s0123.y = s01.y + s23.y; s0123.z = s01.z + s23.z; s0123.w = s01.w + s23.w;
        s4567.x = s45.x + s67.x; s4567.y = s45.y + s67.y; s4567.z = s45.z + s67.z; s4567.w = s45.w + s67.w;
        acc.x += s0123.x + s4567.x;
        acc.y += s0123.y + s4567.y;
        acc.z += s0123.z + s4567.z;
        acc.w += s0123.w + s4567.w;
    }
    for (; i + 4 <= e; i += 4) {
        int s0 = adj[i + 0], s1 = adj[i + 1], s2 = adj[i + 2], s3 = adj[i + 3];
        float4 v0 = *(const float4*)(feat + (size_t)s0 * FEAT + lane * 4);
        float4 v1 = *(const float4*)(feat + (size_t)s1 * FEAT + lane * 4);
        float4 v2 = *(const float4*)(feat + (size_t)s2 * FEAT + lane * 4);
        float4 v3 = *(const float4*)(feat + (size_t)s3 * FEAT + lane * 4);
        acc.x += v0.x + v1.x + v2.x + v3.x;
        acc.y += v0.y + v1.y + v2.y + v3.y;
        acc.z += v0.z + v1.z + v2.z + v3.z;
        acc.w += v0.w + v1.w + v2.w + v3.w;
    }
    for (; i < e; i++) {
        int src = adj[i];
        float4 v = *(const float4*)(feat + (size_t)src * FEAT + lane * 4);
        acc.x += v.x; acc.y += v.y; acc.z += v.z; acc.w += v.w;
    }
    float inv = 1.0f / fmaxf((float)cnt, 1.0f);
    acc.x *= inv; acc.y *= inv; acc.z *= inv; acc.w *= inv;
    *(float4*)(g_agg + (size_t)gw * FEAT + lane * 4) = acc;
}

// ---------------- cp.async double-buffered bf16 3-split wmma GEMM (64x128 tile) ----------------
typedef wmma::fragment<wmma::matrix_a, 16, 16, 16, __nv_bfloat16, wmma::row_major> FragA;
typedef wmma::fragment<wmma::matrix_b, 16, 16, 16, __nv_bfloat16, wmma::col_major> FragB;
typedef wmma::fragment<wmma::accumulator, 16, 16, 16, float> FragC;

#define KP 40          // padded k-stride in smem (elements)
#define BUF_BYTES 30720
#define GEMM_SMEM (2 * BUF_BYTES)   // 61440; epilogue (64x128 f32 = 32768) reuses buf0

__global__ void __launch_bounds__(256) k_gemm(
    const float* __restrict__ xin,
    const float* __restrict__ bias,
    float* __restrict__ out2, const void* __restrict__ pos, int layer2)
{
    extern __shared__ __align__(16) char smraw[];
    const float* selfF = layer2 ? g_h1 : xin;
    const __nv_bfloat16* BH = g_Bhi + (size_t)layer2 * 128 * 256;
    const __nv_bfloat16* BL = g_Blo + (size_t)layer2 * 128 * 256;

    int tid = threadIdx.x;
    int warp = tid >> 5;
    int wm = warp & 1;    // 2 M warps (32 rows each)
    int wn = warp >> 1;   // 4 N warps (32 cols each)
    int m0 = blockIdx.x * 64;

    int r = tid >> 2;          // 0..63 (A tile row)
    int cc = tid & 3;          // 0..3
    bool arow_ok = (m0 + r) < N_NODES;
    uint32_t sbase = smem_u32(smraw);

    #define A_PTR(ch) (((ch) < 4 ? g_agg : selfF) + (size_t)(m0 + r) * FEAT + ((ch) & 3) * 32 + cc * 8)
    #define ISSUE_B(ch, b) do {                                                    \
        int _bk = (ch) * 32;                                                       \
        _Pragma("unroll")                                                          \
        for (int _j = 0; _j < 2; _j++) {                                           \
            int _seg = tid + _j * 256;                                             \
            int _rb = _seg >> 2, _cb = _seg & 3;                                   \
            size_t _bsrc = (size_t)_rb * 256 + _bk + _cb * 8;                      \
            uint32_t _dst = sbase + (b) * BUF_BYTES + 10240 + (_rb * KP + _cb * 8) * 2; \
            CP_ASYNC16(_dst, BH + _bsrc);                                          \
            CP_ASYNC16(_dst + 10240, BL + _bsrc);                                  \
        }                                                                          \
        CP_COMMIT();                                                               \
    } while (0)
    #define STORE_A(b, f0, f1) do {                                                \
        uint4 _hv, _lv;                                                            \
        _hv.x = pack_bf16x2((f0).x, (f0).y);                                       \
        _hv.y = pack_bf16x2((f0).z, (f0).w);                                       \
        _hv.z = pack_bf16x2((f1).x, (f1).y);                                       \
        _hv.w = pack_bf16x2((f1).z, (f1).w);                                       \
        _lv.x = pack_bf16x2((f0).x - bf16v((f0).x), (f0).y - bf16v((f0).y));       \
        _lv.y = pack_bf16x2((f0).z - bf16v((f0).z), (f0).w - bf16v((f0).w));       \
        _lv.z = pack_bf16x2((f1).x - bf16v((f1).x), (f1).y - bf16v((f1).y));       \
        _lv.w = pack_bf16x2((f1).z - bf16v((f1).z), (f1).w - bf16v((f1).w));       \
        __nv_bfloat16* _sA0 = (__nv_bfloat16*)(smraw + (b) * BUF_BYTES);           \
        __nv_bfloat16* _sA1 = (__nv_bfloat16*)(smraw + (b) * BUF_BYTES + 5120);    \
        int _dstA = r * KP + cc * 8;                                               \
        *(uint4*)(_sA0 + _dstA) = _hv;                                             \
        *(uint4*)(_sA1 + _dstA) = _lv;                                             \
    } while (0)

    // prologue: stage chunk 0 into buffer 0
    ISSUE_B(0, 0);
    float4 f0 = make_float4(0.f, 0.f, 0.f, 0.f), f1 = f0;
    if (arow_ok) {
        const float* p = A_PTR(0);
        f0 = *(const float4*)p;
        f1 = *(const float4*)(p + 4);
    }
    STORE_A(0, f0, f1);
    CP_WAIT0();
    __syncthreads();

    FragC c[2][2];
    #pragma unroll
    for (int i = 0; i < 2; i++)
        #pragma unroll
        for (int j = 0; j < 2; j++)
            wmma::fill_fragment(c[i][j], 0.0f);

    #pragma unroll 1
    for (int ch = 0; ch < 8; ch++) {
        int cur = ch & 1, nxt = cur ^ 1;

        float4 n0 = make_float4(0.f, 0.f, 0.f, 0.f), n1 = n0;
        if (ch < 7) {
            ISSUE_B(ch + 1, nxt);
            if (arow_ok) {
                const float* p = A_PTR(ch + 1);
                n0 = *(const float4*)p;
                n1 = *(const float4*)(p + 4);
            }
        }

        __nv_bfloat16* sA0 = (__nv_bfloat16*)(smraw + cur * BUF_BYTES);
        __nv_bfloat16* sA1 = (__nv_bfloat16*)(smraw + cur * BUF_BYTES + 5120);
        __nv_bfloat16* sB0 = (__nv_bfloat16*)(smraw + cur * BUF_BYTES + 10240);
        __nv_bfloat16* sB1 = (__nv_bfloat16*)(smraw + cur * BUF_BYTES + 20480);
        #pragma unroll
        for (int ks = 0; ks < 2; ks++) {
            FragA ah[2], al[2];
            #pragma unroll
            for (int i = 0; i < 2; i++) {
                wmma::load_matrix_sync(ah[i], sA0 + (wm * 32 + i * 16) * KP + ks * 16, KP);
                wmma::load_matrix_sync(al[i], sA1 + (wm * 32 + i * 16) * KP + ks * 16, KP);
            }
            FragB bh[2], bl[2];
            #pragma unroll
            for (int j = 0; j < 2; j++) {
                wmma::load_matrix_sync(bh[j], sB0 + (wn * 32 + j * 16) * KP + ks * 16, KP);
                wmma::load_matrix_sync(bl[j], sB1 + (wn * 32 + j * 16) * KP + ks * 16, KP);
            }
            #pragma unroll
            for (int i = 0; i < 2; i++)
                #pragma unroll
                for (int j = 0; j < 2; j++) {
                    wmma::mma_sync(c[i][j], ah[i], bh[j], c[i][j]);
                    wmma::mma_sync(c[i][j], al[i], bh[j], c[i][j]);
                    wmma::mma_sync(c[i][j], ah[i], bl[j], c[i][j]);
                }
        }

        if (ch < 7) {
            STORE_A(nxt, n0, n1);
            CP_WAIT0();
        }
        __syncthreads();
    }

    // epilogue: single-pass 64 x 128 f32 through smem (reuses buffers)
    float* cs = (float*)smraw;
    int is64 = g_idx64;
    #pragma unroll
    for (int i = 0; i < 2; i++)
        #pragma unroll
        for (int j = 0; j < 2; j++)
            wmma::store_matrix_sync(&cs[(wm * 32 + i * 16) * 128 + wn * 32 + j * 16],
                                    c[i][j], 128, wmma::mem_row_major);
    __syncthreads();

    #pragma unroll
    for (int it = 0; it < 8; it++) {
        int idx = (it * 256 + tid) * 4;    // 0..8188 -> 64x128
        int m = idx >> 7;
        int n = idx & 127;
        int row = m0 + m;
        if (row < N_NODES) {
            float v0 = fmaxf(cs[idx + 0] + bias[n + 0], 0.0f);
            float v1 = fmaxf(cs[idx + 1] + bias[n + 1], 0.0f);
            float v2 = fmaxf(cs[idx + 2] + bias[n + 2], 0.0f);
            float v3 = fmaxf(cs[idx + 3] + bias[n + 3], 0.0f);
            if (!layer2) {
                *(float4*)(g_h1 + (size_t)row * FEAT + n) = make_float4(v0, v1, v2, v3);
            } else {
                long long orow = (long long)load_idx(pos, row, is64);
                *(float4*)(out2 + (size_t)orow * FEAT + n) = make_float4(v0, v1, v2, v3);
            }
        }
    }
}

// ---------------- launch ----------------
extern "C" void kernel_launch(void* const* d_in, const int* in_sizes, int n_in,
                              void* d_out, int out_size) {
    int wi = (n_in >= 10) ? 4 : 3;
    const float* x   = (const float*)d_in[0];
    const void*  ei  = d_in[1];
    const void*  pos = d_in[2];
    const float* Wl1 = (const float*)d_in[wi + 0];
    const float* Wr1 = (const float*)d_in[wi + 1];
    const float* b1  = (const float*)d_in[wi + 2];
    const float* Wl2 = (const float*)d_in[wi + 3];
    const float* Wr2 = (const float*)d_in[wi + 4];
    const float* b2  = (const float*)d_in[wi + 5];
    float* out = (float*)d_out;

    static cudaStream_t s_side = nullptr;
    static cudaEvent_t ev_fork = nullptr, ev_join = nullptr;
    static int done_init = 0;
    if (!done_init) {
        cudaFuncSetAttribute(k_gemm, cudaFuncAttributeMaxDynamicSharedMemorySize, GEMM_SMEM);
        cudaStreamCreateWithFlags(&s_side, cudaStreamNonBlocking);
        cudaEventCreateWithFlags(&ev_fork, cudaEventDisableTiming);
        cudaEventCreateWithFlags(&ev_join, cudaEventDisableTiming);
        done_init = 1;
    }

    // main stream: detect + reset feeds everything
    k_detect_reset<<<(N_NODES + 255) / 256, 256>>>((const unsigned*)ei, pos);

    // fork: init (weights + out-zero) runs beside the adjacency build
    cudaEventRecord(ev_fork, 0);
    cudaStreamWaitEvent(s_side, ev_fork, 0);
    k_init<<<2048, 256, 0, s_side>>>(out, out_size, Wl1, Wr1, Wl2, Wr2);
    cudaEventRecord(ev_join, s_side);

    // critical path: bucket adjacency build + layer-1 aggregation
    k_build<<<(N_EDGES + 255) / 256, 256>>>(ei);
    k_agg<<<(N_NODES + 7) / 8, 256>>>(x, 0);

    // join: gemm1 needs weights (init)
    cudaStreamWaitEvent(0, ev_join, 0);
    k_gemm<<<NTILES, 256, GEMM_SMEM>>>(x, b1, nullptr, nullptr, 0);
    k_agg<<<(N_NODES + 7) / 8, 256>>>(x, 1);
    k_gemm<<<NTILES, 256, GEMM_SMEM>>>(x, b2, out, pos, 1);
}